// round 9
// baseline (speedup 1.0000x reference)
#include <cuda_runtime.h>
#include <math.h>

#define NS 50000
#define NA 50000
#define ES 1000000
#define EA 500000
#define HD 64

// Scratch (allocation-free rule): device globals, 16B-aligned for v4 atomics.
__device__ __align__(16) float g_sum_u[NS * HD];
__device__ __align__(16) float g_sum_x[NS * HD];
__device__ float g_deg[NS];

// FMA-only reciprocal: integer magic seed + 3 Newton iterations (~1e-8 rel).
__device__ __forceinline__ float rcp_fma(float d) {
    float r = __int_as_float(0x7EF311C3 - __float_as_int(d));
    r = r * fmaf(-d, r, 2.0f);
    r = r * fmaf(-d, r, 2.0f);
    r = r * fmaf(-d, r, 2.0f);
    return r;
}

// MUFU-free tanh: rational approx x*P(x2)/Q(x2), clamp +-7.90531 (~1e-7 acc).
__device__ __forceinline__ float my_tanh(float v) {
    float x = fminf(fmaxf(v, -7.90531110f), 7.90531110f);
    float x2 = x * x;
    float p = -2.76076847742355e-16f;
    p = fmaf(p, x2, 2.00018790482477e-13f);
    p = fmaf(p, x2, -8.60467152213735e-11f);
    p = fmaf(p, x2, 5.12229709037114e-08f);
    p = fmaf(p, x2, 1.48572235717979e-05f);
    p = fmaf(p, x2, 6.37261928875436e-04f);
    p = fmaf(p, x2, 4.89352455891786e-03f);
    float q = 1.19825839466702e-06f;
    q = fmaf(q, x2, 1.18534705686654e-04f);
    q = fmaf(q, x2, 2.26843463243900e-03f);
    q = fmaf(q, x2, 4.89352518554385e-03f);
    return (x * p) * rcp_fma(q);
}

__device__ __forceinline__ void red_add4(float* p, float a, float b, float c, float d) {
    asm volatile("red.global.add.v4.f32 [%0], {%1,%2,%3,%4};"
                 :: "l"(p), "f"(a), "f"(b), "f"(c), "f"(d) : "memory");
}

// Dual accumulate: one weight float4 feeds both edges (32 FMA per 1 LDS.128).
__device__ __forceinline__ void accum16x2(float* accA, float* accB, const float* wrow,
                                          float vA, float vB) {
#pragma unroll
    for (int i = 0; i < 16; i += 4) {
        float4 w = *reinterpret_cast<const float4*>(wrow + i);
        accA[i + 0] += vA * w.x; accA[i + 1] += vA * w.y;
        accA[i + 2] += vA * w.z; accA[i + 3] += vA * w.w;
        accB[i + 0] += vB * w.x; accB[i + 1] += vB * w.y;
        accB[i + 2] += vB * w.z; accB[i + 3] += vB * w.w;
    }
}

// Weight layout in smem: row k occupies 80 floats, columns stored as slot*20 + i (i<16).
#define WROW 80

__device__ void cp_w_pad(float* dst, const float* __restrict__ src,
                         int src_rows, int dst_rows, int tid, int nt) {
    for (int idx = tid; idx < dst_rows * WROW; idx += nt) {
        int k = idx / WROW, c = idx % WROW;
        int slot = c / 20, i = c % 20;
        float v = 0.0f;
        if (i < 16 && k < src_rows) v = src[k * 64 + slot * 16 + i];
        dst[idx] = v;
    }
}
__device__ void cp_b(float* dst, const float* __restrict__ src, int tid, int nt) {
    for (int i = tid; i < 64; i += nt) dst[i] = src[i];
}

// Generic dual-edge matvec chunk: acc += W[k0..k0+n) rows dotted with z values.
// Outer loop kept small (unroll 2) to bound compiled code size.
__device__ __forceinline__ void matvec16x2(float* accA, float* accB, const float* wslot,
                                           const float* zrowA, const float* zrowB,
                                           int nrows4) {
#pragma unroll 2
    for (int k4 = 0; k4 < nrows4; k4++) {
        float4 a = *reinterpret_cast<const float4*>(zrowA + k4 * 4);
        float4 b = *reinterpret_cast<const float4*>(zrowB + k4 * 4);
        const float* w = wslot + (k4 * 4) * WROW;
        accum16x2(accA, accB, w + 0 * WROW, a.x, b.x);
        accum16x2(accA, accB, w + 1 * WROW, a.y, b.y);
        accum16x2(accA, accB, w + 2 * WROW, a.z, b.z);
        accum16x2(accA, accB, w + 3 * WROW, a.w, b.w);
    }
}

__device__ __forceinline__ void load_bias16x2(float* accA, float* accB,
                                              const float* sB, int slot) {
#pragma unroll
    for (int i = 0; i < 16; i += 4) {
        float4 bv = *reinterpret_cast<const float4*>(sB + slot * 16 + i);
        accA[i] = bv.x; accA[i + 1] = bv.y; accA[i + 2] = bv.z; accA[i + 3] = bv.w;
        accB[i] = bv.x; accB[i + 1] = bv.y; accB[i + 2] = bv.z; accB[i + 3] = bv.w;
    }
}

__device__ __forceinline__ void tanh_store16x2(const float* accA, const float* accB,
                                               float* zrowA, float* zrowB, int slot) {
    float4* zsA = reinterpret_cast<float4*>(zrowA + slot * 16);
    float4* zsB = reinterpret_cast<float4*>(zrowB + slot * 16);
#pragma unroll 2
    for (int i = 0; i < 16; i += 4) {
        zsA[i >> 2] = make_float4(my_tanh(accA[i]), my_tanh(accA[i + 1]),
                                  my_tanh(accA[i + 2]), my_tanh(accA[i + 3]));
        zsB[i >> 2] = make_float4(my_tanh(accB[i]), my_tanh(accB[i + 1]),
                                  my_tanh(accB[i + 2]), my_tanh(accB[i + 3]));
    }
}

// Layers 2+3 for one slot, two edges at once. acc holds layer-1 preact on entry.
__device__ void layers23_q2(float* accA, float* accB,
                            const float* sW2, const float* sB2,
                            const float* sW3, const float* sB3,
                            float* zrowA, float* zrowB, int slot) {
    tanh_store16x2(accA, accB, zrowA, zrowB, slot);
    __syncwarp();
    load_bias16x2(accA, accB, sB2, slot);
    matvec16x2(accA, accB, sW2 + slot * 20, zrowA, zrowB, 16);
    __syncwarp();
    tanh_store16x2(accA, accB, zrowA, zrowB, slot);
    __syncwarp();
    load_bias16x2(accA, accB, sB3, slot);
    matvec16x2(accA, accB, sW3 + slot * 20, zrowA, zrowB, 16);
    __syncwarp();
}

__device__ __forceinline__ void scatter16(float* outp, const float* acc) {
    red_add4(outp + 0,  acc[0],  acc[1],  acc[2],  acc[3]);
    red_add4(outp + 4,  acc[4],  acc[5],  acc[6],  acc[7]);
    red_add4(outp + 8,  acc[8],  acc[9],  acc[10], acc[11]);
    red_add4(outp + 12, acc[12], acc[13], acc[14], acc[15]);
}

// ---------------------------------------------------------------------------
__global__ void zero_kernel(void) {
    int i = blockIdx.x * blockDim.x + threadIdx.x;
    if (i < NS * HD) { g_sum_u[i] = 0.0f; g_sum_x[i] = 0.0f; }
    if (i < NS) g_deg[i] = 0.0f;
}

// ---------------------------------------------------------------------------
// s2s: in = [ps_src(2), ps_dst(2), dis(1), x[src](8), h[src](64)] = 77 -> pad 80
// 512 threads, 2 edges/thread -> 256 edges/tile. z rows: group q uses q and q+128.
#define S2S_ZSTRIDE 100
#define S2S_SMF (6400 + 64 + 5120 + 64 + 5120 + 64 + 256 * S2S_ZSTRIDE)

__device__ void s2s_gather(
    float* zrow, int s, int d, int ec, int slot,
    const float* __restrict__ pos_state, const float* __restrict__ xin,
    const float* __restrict__ h, const float* __restrict__ edis) {
    const float4* h4 = reinterpret_cast<const float4*>(h + (size_t)s * 64);
#pragma unroll 2
    for (int i = 0; i < 4; i++) {
        float4 v = h4[slot * 4 + i];
        int b = 13 + slot * 16 + i * 4;
        zrow[b] = v.x; zrow[b + 1] = v.y; zrow[b + 2] = v.z; zrow[b + 3] = v.w;
    }
    if (slot == 0) {
        float2 ps_ = *reinterpret_cast<const float2*>(pos_state + 2 * (size_t)s);
        float2 pd_ = *reinterpret_cast<const float2*>(pos_state + 2 * (size_t)d);
        zrow[0] = ps_.x; zrow[1] = ps_.y; zrow[2] = pd_.x; zrow[3] = pd_.y;
        zrow[4] = edis[ec];
    } else if (slot == 1) {
        const float4* x4 = reinterpret_cast<const float4*>(xin + 8 * (size_t)s);
        float4 a = x4[0], b4 = x4[1];
        zrow[5] = a.x; zrow[6] = a.y; zrow[7] = a.z; zrow[8] = a.w;
        zrow[9] = b4.x; zrow[10] = b4.y; zrow[11] = b4.z; zrow[12] = b4.w;
    }
}

__global__ void __launch_bounds__(512) s2s_kernel(
    const float* __restrict__ pos_state, const float* __restrict__ xin,
    const float* __restrict__ h,
    const int* __restrict__ esrc, const int* __restrict__ edst,
    const float* __restrict__ edis,
    const float* __restrict__ W1, const float* __restrict__ B1,
    const float* __restrict__ W2, const float* __restrict__ B2,
    const float* __restrict__ W3, const float* __restrict__ B3) {
    extern __shared__ float sm[];
    float* sW1 = sm;
    float* sB1 = sW1 + 6400;
    float* sW2 = sB1 + 64;
    float* sB2 = sW2 + 5120;
    float* sW3 = sB2 + 64;
    float* sB3 = sW3 + 5120;
    float* zbase = sB3 + 64;
    int tid = threadIdx.x, nt = blockDim.x;
    cp_w_pad(sW1, W1, 77, 80, tid, nt);
    cp_b(sB1, B1, tid, nt);
    cp_w_pad(sW2, W2, 64, 64, tid, nt);
    cp_b(sB2, B2, tid, nt);
    cp_w_pad(sW3, W3, 64, 64, tid, nt);
    cp_b(sB3, B3, tid, nt);
    for (int i = tid; i < 256 * S2S_ZSTRIDE; i += nt) zbase[i] = 0.0f;
    __syncthreads();

    int q = tid >> 2, slot = tid & 3;
    float* zrowA = zbase + q * S2S_ZSTRIDE;
    float* zrowB = zbase + (q + 128) * S2S_ZSTRIDE;
    const float* w1s = sW1 + slot * 20;

    for (int base = blockIdx.x * 256; base < ES; base += gridDim.x * 256) {
        int eA = base + q, eB = base + q + 128;
        bool actA = eA < ES, actB = eB < ES;
        int ecA = actA ? eA : (ES - 1);
        int ecB = actB ? eB : (ES - 1);
        int sA = esrc[ecA], dA = edst[ecA];
        int sB_ = esrc[ecB], dB = edst[ecB];

        s2s_gather(zrowA, sA, dA, ecA, slot, pos_state, xin, h, edis);
        s2s_gather(zrowB, sB_, dB, ecB, slot, pos_state, xin, h, edis);
        __syncwarp();

        float accA[16], accB[16];
        load_bias16x2(accA, accB, sB1, slot);
        matvec16x2(accA, accB, w1s, zrowA, zrowB, 20);
        __syncwarp();
        layers23_q2(accA, accB, sW2, sB2, sW3, sB3, zrowA, zrowB, slot);

        if (actA) {
            scatter16(g_sum_x + (size_t)dA * 64 + slot * 16, accA);
            if (slot == 0) atomicAdd(g_deg + dA, 1.0f);
        }
        if (actB) {
            scatter16(g_sum_x + (size_t)dB * 64 + slot * 16, accB);
            if (slot == 0) atomicAdd(g_deg + dB, 1.0f);
        }
    }
}

// ---------------------------------------------------------------------------
// a2s: in = [pa_src(2), ps_dst(2), dis(1), u[src](8)] = 13 -> pad 16.
#define A2S_ZSTRIDE 68
#define A2S_SMF (1280 + 64 + 5120 + 64 + 5120 + 64 + 256 * A2S_ZSTRIDE)

__device__ void a2s_gather(
    float* zrow, int s, int d, int ec, int slot,
    const float* __restrict__ pos_state, const float* __restrict__ pos_action,
    const float* __restrict__ u, const float* __restrict__ edis) {
    if (slot == 0) {
        float2 pa_ = *reinterpret_cast<const float2*>(pos_action + 2 * (size_t)s);
        float2 pd_ = *reinterpret_cast<const float2*>(pos_state + 2 * (size_t)d);
        zrow[0] = pa_.x; zrow[1] = pa_.y; zrow[2] = pd_.x; zrow[3] = pd_.y;
        zrow[4] = edis[ec];
    } else if (slot == 1) {
        const float4* u4 = reinterpret_cast<const float4*>(u + 8 * (size_t)s);
        float4 a = u4[0], b4 = u4[1];
        zrow[5] = a.x; zrow[6] = a.y; zrow[7] = a.z; zrow[8] = a.w;
        zrow[9] = b4.x; zrow[10] = b4.y; zrow[11] = b4.z; zrow[12] = b4.w;
    }
}

__global__ void __launch_bounds__(512) a2s_kernel(
    const float* __restrict__ pos_state, const float* __restrict__ pos_action,
    const float* __restrict__ u,
    const int* __restrict__ esrc, const int* __restrict__ edst,
    const float* __restrict__ edis,
    const float* __restrict__ W1, const float* __restrict__ B1,
    const float* __restrict__ W2, const float* __restrict__ B2,
    const float* __restrict__ W3, const float* __restrict__ B3) {
    extern __shared__ float sm[];
    float* sW1 = sm;
    float* sB1 = sW1 + 1280;
    float* sW2 = sB1 + 64;
    float* sB2 = sW2 + 5120;
    float* sW3 = sB2 + 64;
    float* sB3 = sW3 + 5120;
    float* zbase = sB3 + 64;
    int tid = threadIdx.x, nt = blockDim.x;
    cp_w_pad(sW1, W1, 13, 16, tid, nt);
    cp_b(sB1, B1, tid, nt);
    cp_w_pad(sW2, W2, 64, 64, tid, nt);
    cp_b(sB2, B2, tid, nt);
    cp_w_pad(sW3, W3, 64, 64, tid, nt);
    cp_b(sB3, B3, tid, nt);
    for (int i = tid; i < 256 * A2S_ZSTRIDE; i += nt) zbase[i] = 0.0f;
    __syncthreads();

    int q = tid >> 2, slot = tid & 3;
    float* zrowA = zbase + q * A2S_ZSTRIDE;
    float* zrowB = zbase + (q + 128) * A2S_ZSTRIDE;
    const float* w1s = sW1 + slot * 20;

    for (int base = blockIdx.x * 256; base < EA; base += gridDim.x * 256) {
        int eA = base + q, eB = base + q + 128;
        bool actA = eA < EA, actB = eB < EA;
        int ecA = actA ? eA : (EA - 1);
        int ecB = actB ? eB : (EA - 1);
        int sA = esrc[ecA], dA = edst[ecA];
        int sB_ = esrc[ecB], dB = edst[ecB];

        a2s_gather(zrowA, sA, dA, ecA, slot, pos_state, pos_action, u, edis);
        a2s_gather(zrowB, sB_, dB, ecB, slot, pos_state, pos_action, u, edis);
        __syncwarp();

        float accA[16], accB[16];
        load_bias16x2(accA, accB, sB1, slot);
        matvec16x2(accA, accB, w1s, zrowA, zrowB, 4);
        __syncwarp();
        layers23_q2(accA, accB, sW2, sB2, sW3, sB3, zrowA, zrowB, slot);

        if (actA) scatter16(g_sum_u + (size_t)dA * 64 + slot * 16, accA);
        if (actB) scatter16(g_sum_u + (size_t)dB * 64 + slot * 16, accB);
    }
}

// ---------------------------------------------------------------------------
// upd: in = [pos(2), h(64), sum_u(64), mean_x(64), x(8)] = 202 -> pad 204.
// Inputs gathered into z rows (each slot loads quarters of h/sum_u/sum_x),
// then a single generic matvec -> small compiled footprint.
#define UPD_ZSTRIDE 212
#define UPD_W1R 204
// smem floats: W1 204*80=16320, B1 64, W2 5120, B2 64, W3 5120, B3 64, Z 128*212=27136
#define UPD_SMF (16320 + 64 + 5120 + 64 + 5120 + 64 + 128 * UPD_ZSTRIDE)

__global__ void __launch_bounds__(512) upd_kernel(
    const float* __restrict__ pos_state, const float* __restrict__ h,
    const float* __restrict__ xin,
    const float* __restrict__ W1, const float* __restrict__ B1,
    const float* __restrict__ W2, const float* __restrict__ B2,
    const float* __restrict__ W3, const float* __restrict__ B3,
    float* __restrict__ out) {
    extern __shared__ float sm[];
    float* sW1 = sm;
    float* sB1 = sW1 + 16320;
    float* sW2 = sB1 + 64;
    float* sB2 = sW2 + 5120;
    float* sW3 = sB2 + 64;
    float* sB3 = sW3 + 5120;
    float* zbase = sB3 + 64;
    int tid = threadIdx.x, nt = blockDim.x;
    cp_w_pad(sW1, W1, 202, UPD_W1R, tid, nt);
    cp_b(sB1, B1, tid, nt);
    cp_w_pad(sW2, W2, 64, 64, tid, nt);
    cp_b(sB2, B2, tid, nt);
    cp_w_pad(sW3, W3, 64, 64, tid, nt);
    cp_b(sB3, B3, tid, nt);
    for (int i = tid; i < 128 * UPD_ZSTRIDE; i += nt) zbase[i] = 0.0f;
    __syncthreads();

    int q = tid >> 2, slot = tid & 3;
    float* zrow = zbase + q * UPD_ZSTRIDE;  // one node per thread-group (128/tile)
    const float* w1s = sW1 + slot * 20;

    for (int base = blockIdx.x * 128; base < NS; base += gridDim.x * 128) {
        int n = base + q;
        bool act = n < NS;
        int nc = act ? n : (NS - 1);

        // gather 202 inputs into zrow
        {
            const float4* h4 = reinterpret_cast<const float4*>(h + 64 * (size_t)nc);
            const float4* su4 = reinterpret_cast<const float4*>(g_sum_u + 64 * (size_t)nc);
            const float4* sx4 = reinterpret_cast<const float4*>(g_sum_x + 64 * (size_t)nc);
            float inv = rcp_fma(fmaxf(g_deg[nc], 1.0f));
#pragma unroll 2
            for (int i = 0; i < 4; i++) {
                float4 v = h4[slot * 4 + i];
                int b = 2 + slot * 16 + i * 4;
                zrow[b] = v.x; zrow[b + 1] = v.y; zrow[b + 2] = v.z; zrow[b + 3] = v.w;
            }
#pragma unroll 2
            for (int i = 0; i < 4; i++) {
                float4 v = su4[slot * 4 + i];
                int b = 66 + slot * 16 + i * 4;
                zrow[b] = v.x; zrow[b + 1] = v.y; zrow[b + 2] = v.z; zrow[b + 3] = v.w;
            }
#pragma unroll 2
            for (int i = 0; i < 4; i++) {
                float4 v = sx4[slot * 4 + i];
                int b = 130 + slot * 16 + i * 4;
                zrow[b] = v.x * inv; zrow[b + 1] = v.y * inv;
                zrow[b + 2] = v.z * inv; zrow[b + 3] = v.w * inv;
            }
            if (slot == 0) {
                float2 ps_ = *reinterpret_cast<const float2*>(pos_state + 2 * (size_t)nc);
                zrow[0] = ps_.x; zrow[1] = ps_.y;
            } else if (slot == 1) {
                const float4* x4 = reinterpret_cast<const float4*>(xin + 8 * (size_t)nc);
                float4 a = x4[0], b4 = x4[1];
                zrow[194] = a.x; zrow[195] = a.y; zrow[196] = a.z; zrow[197] = a.w;
                zrow[198] = b4.x; zrow[199] = b4.y; zrow[200] = b4.z; zrow[201] = b4.w;
            }
        }
        __syncwarp();

        float accA[16], accB[16];  // accB is a dummy duplicate (same node) to reuse code
        load_bias16x2(accA, accB, sB1, slot);
        matvec16x2(accA, accB, w1s, zrow, zrow, UPD_W1R / 4);
        __syncwarp();
        layers23_q2(accA, accB, sW2, sB2, sW3, sB3, zrow, zrow, slot);

        if (act) {
            float4* o4 = reinterpret_cast<float4*>(out + 64 * (size_t)n + slot * 16);
#pragma unroll
            for (int j = 0; j < 4; j++)
                o4[j] = make_float4(accA[4 * j], accA[4 * j + 1], accA[4 * j + 2], accA[4 * j + 3]);
        }
    }
}

// ---------------------------------------------------------------------------
extern "C" void kernel_launch(void* const* d_in, const int* in_sizes, int n_in,
                              void* d_out, int out_size) {
    const float* pos_state  = (const float*)d_in[0];
    const float* pos_action = (const float*)d_in[1];
    const float* h          = (const float*)d_in[2];
    const float* x          = (const float*)d_in[3];
    const float* u          = (const float*)d_in[4];
    const int*   a2s_src    = (const int*)d_in[5];
    const int*   a2s_dst    = (const int*)d_in[6];
    const float* a2s_dis    = (const float*)d_in[7];
    const int*   s2s_src    = (const int*)d_in[8];
    const int*   s2s_dst    = (const int*)d_in[9];
    const float* s2s_dis    = (const float*)d_in[10];
    const float* u2h_w1 = (const float*)d_in[11];
    const float* u2h_b1 = (const float*)d_in[12];
    const float* u2h_w2 = (const float*)d_in[13];
    const float* u2h_b2 = (const float*)d_in[14];
    const float* u2h_w3 = (const float*)d_in[15];
    const float* u2h_b3 = (const float*)d_in[16];
    const float* x2h_w1 = (const float*)d_in[17];
    const float* x2h_b1 = (const float*)d_in[18];
    const float* x2h_w2 = (const float*)d_in[19];
    const float* x2h_b2 = (const float*)d_in[20];
    const float* x2h_w3 = (const float*)d_in[21];
    const float* x2h_b3 = (const float*)d_in[22];
    const float* upd_w1 = (const float*)d_in[23];
    const float* upd_b1 = (const float*)d_in[24];
    const float* upd_w2 = (const float*)d_in[25];
    const float* upd_b2 = (const float*)d_in[26];
    const float* upd_w3 = (const float*)d_in[27];
    const float* upd_b3 = (const float*)d_in[28];
    float* out = (float*)d_out;

    const int S2S_SMEM = S2S_SMF * 4;
    const int A2S_SMEM = A2S_SMF * 4;
    const int UPD_SMEM = UPD_SMF * 4;
    cudaFuncSetAttribute(s2s_kernel, cudaFuncAttributeMaxDynamicSharedMemorySize, S2S_SMEM);
    cudaFuncSetAttribute(a2s_kernel, cudaFuncAttributeMaxDynamicSharedMemorySize, A2S_SMEM);
    cudaFuncSetAttribute(upd_kernel, cudaFuncAttributeMaxDynamicSharedMemorySize, UPD_SMEM);

    zero_kernel<<<(NS * HD + 255) / 256, 256>>>();

    a2s_kernel<<<148, 512, A2S_SMEM>>>(
        pos_state, pos_action, u, a2s_src, a2s_dst, a2s_dis,
        u2h_w1, u2h_b1, u2h_w2, u2h_b2, u2h_w3, u2h_b3);

    s2s_kernel<<<148, 512, S2S_SMEM>>>(
        pos_state, x, h, s2s_src, s2s_dst, s2s_dis,
        x2h_w1, x2h_b1, x2h_w2, x2h_b2, x2h_w3, x2h_b3);

    upd_kernel<<<148, 512, UPD_SMEM>>>(
        pos_state, h, x,
        upd_w1, upd_b1, upd_w2, upd_b2, upd_w3, upd_b3,
        out);
}

// round 13
// speedup vs baseline: 4.3253x; 4.3253x over previous
#include <cuda_runtime.h>
#include <cuda_bf16.h>
#include <stdint.h>

#define NS 50000
#define ES 1000000
#define EA 500000

// Scratch (allocation-free rule): device globals, 16B-aligned.
__device__ __align__(16) float g_sum_u[NS * 64];
__device__ __align__(16) float g_sum_x[NS * 64];
__device__ float g_deg[NS];

// ---------------------------------------------------------------------------
__device__ __forceinline__ float rcp_fma(float d) {
    float r = __int_as_float(0x7EF311C3 - __float_as_int(d));
    r = r * fmaf(-d, r, 2.0f);
    r = r * fmaf(-d, r, 2.0f);
    r = r * fmaf(-d, r, 2.0f);
    return r;
}
__device__ __forceinline__ float my_tanh(float v) {
    float x = fminf(fmaxf(v, -7.90531110f), 7.90531110f);
    float x2 = x * x;
    float p = -2.76076847742355e-16f;
    p = fmaf(p, x2, 2.00018790482477e-13f);
    p = fmaf(p, x2, -8.60467152213735e-11f);
    p = fmaf(p, x2, 5.12229709037114e-08f);
    p = fmaf(p, x2, 1.48572235717979e-05f);
    p = fmaf(p, x2, 6.37261928875436e-04f);
    p = fmaf(p, x2, 4.89352455891786e-03f);
    float q = 1.19825839466702e-06f;
    q = fmaf(q, x2, 1.18534705686654e-04f);
    q = fmaf(q, x2, 2.26843463243900e-03f);
    q = fmaf(q, x2, 4.89352518554385e-03f);
    return (x * p) * rcp_fma(q);
}
// split pair (a=even idx, b=odd idx) into bf16x2 hi/lo planes (low half = even)
__device__ __forceinline__ void split2(float a, float b, uint32_t& hi, uint32_t& lo) {
    __nv_bfloat16 ah = __float2bfloat16(a), bh = __float2bfloat16(b);
    float ar = a - __bfloat162float(ah), br = b - __bfloat162float(bh);
    __nv_bfloat16 al = __float2bfloat16(ar), bl = __float2bfloat16(br);
    hi = ((uint32_t)__bfloat16_as_ushort(bh) << 16) | (uint32_t)__bfloat16_as_ushort(ah);
    lo = ((uint32_t)__bfloat16_as_ushort(bl) << 16) | (uint32_t)__bfloat16_as_ushort(al);
}
__device__ __forceinline__ void mma_bf16(float c[4], uint32_t a0, uint32_t a1,
                                         uint32_t a2, uint32_t a3,
                                         uint32_t b0, uint32_t b1) {
    asm volatile("mma.sync.aligned.m16n8k16.row.col.f32.bf16.bf16.f32 "
        "{%0,%1,%2,%3}, {%4,%5,%6,%7}, {%8,%9}, {%0,%1,%2,%3};"
        : "+f"(c[0]), "+f"(c[1]), "+f"(c[2]), "+f"(c[3])
        : "r"(a0), "r"(a1), "r"(a2), "r"(a3), "r"(b0), "r"(b1));
}
__device__ __forceinline__ void red2(float* p, float a, float b) {
    asm volatile("red.global.add.v2.f32 [%0], {%1,%2};" :: "l"(p), "f"(a), "f"(b) : "memory");
}

// Stage W[k][64] -> Wt[n][kpad] (bf16 hi/lo words), row stride WSw words.
__device__ void stage_W(const float* __restrict__ W, uint32_t* wh, uint32_t* wl,
                        int Kin, int WSw, int tid, int nt) {
    for (int idx = tid; idx < 64 * WSw; idx += nt) {
        int n = idx / WSw, kw = idx % WSw;
        int k0 = kw * 2;
        float v0 = (k0 < Kin) ? W[(size_t)k0 * 64 + n] : 0.0f;
        float v1 = (k0 + 1 < Kin) ? W[(size_t)(k0 + 1) * 64 + n] : 0.0f;
        uint32_t hi, lo;
        split2(v0, v1, hi, lo);
        wh[idx] = hi; wl[idx] = lo;
    }
}

// Layer with A in smem (3-term bf16-split accumulate).
__device__ __forceinline__ void layer_smem(float acc[8][4],
    const uint32_t* Ah, const uint32_t* Al, int ASw, int rowbase,
    const uint32_t* Wh, const uint32_t* Wl, int WSw, int kchunks, int lane)
{
    int g = lane >> 2, c = lane & 3;
#pragma unroll
    for (int i = 0; i < 8; i++)
#pragma unroll
        for (int j = 0; j < 4; j++) acc[i][j] = 0.0f;
    const uint32_t* a0p = Ah + (rowbase + g) * ASw + c;
    const uint32_t* a1p = Ah + (rowbase + g + 8) * ASw + c;
    const uint32_t* l0p = Al + (rowbase + g) * ASw + c;
    const uint32_t* l1p = Al + (rowbase + g + 8) * ASw + c;
    for (int kc = 0; kc < kchunks; kc++) {
        uint32_t ah0 = a0p[kc * 8], ah1 = a1p[kc * 8];
        uint32_t ah2 = a0p[kc * 8 + 4], ah3 = a1p[kc * 8 + 4];
        uint32_t al0 = l0p[kc * 8], al1 = l1p[kc * 8];
        uint32_t al2 = l0p[kc * 8 + 4], al3 = l1p[kc * 8 + 4];
#pragma unroll
        for (int nt2 = 0; nt2 < 8; nt2++) {
            const uint32_t* bh = Wh + (nt2 * 8 + g) * WSw + kc * 8 + c;
            const uint32_t* bl = Wl + (nt2 * 8 + g) * WSw + kc * 8 + c;
            uint32_t bh0 = bh[0], bh1 = bh[4];
            uint32_t bl0 = bl[0], bl1 = bl[4];
            mma_bf16(acc[nt2], ah0, ah1, ah2, ah3, bh0, bh1);
            mma_bf16(acc[nt2], ah0, ah1, ah2, ah3, bl0, bl1);
            mma_bf16(acc[nt2], al0, al1, al2, al3, bh0, bh1);
        }
    }
}

// Layer with activations in registers (C-frag == A-frag layout), K=64 (4 chunks).
__device__ __forceinline__ void layer_regs(float acc[8][4],
    const uint32_t zh[16], const uint32_t zl[16],
    const uint32_t* Wh, const uint32_t* Wl, int lane)   // WSw = 36
{
    int g = lane >> 2, c = lane & 3;
#pragma unroll
    for (int i = 0; i < 8; i++)
#pragma unroll
        for (int j = 0; j < 4; j++) acc[i][j] = 0.0f;
#pragma unroll
    for (int kc = 0; kc < 4; kc++) {
        uint32_t ah0 = zh[4 * kc + 0], ah1 = zh[4 * kc + 1];
        uint32_t ah2 = zh[4 * kc + 2], ah3 = zh[4 * kc + 3];
        uint32_t al0 = zl[4 * kc + 0], al1 = zl[4 * kc + 1];
        uint32_t al2 = zl[4 * kc + 2], al3 = zl[4 * kc + 3];
#pragma unroll
        for (int nt2 = 0; nt2 < 8; nt2++) {
            const uint32_t* bh = Wh + (nt2 * 8 + g) * 36 + kc * 8 + c;
            const uint32_t* bl = Wl + (nt2 * 8 + g) * 36 + kc * 8 + c;
            uint32_t bh0 = bh[0], bh1 = bh[4];
            uint32_t bl0 = bl[0], bl1 = bl[4];
            mma_bf16(acc[nt2], ah0, ah1, ah2, ah3, bh0, bh1);
            mma_bf16(acc[nt2], ah0, ah1, ah2, ah3, bl0, bl1);
            mma_bf16(acc[nt2], al0, al1, al2, al3, bh0, bh1);
        }
    }
}

// bias + tanh + bf16-split pack: acc -> next-layer A-frags (registers).
__device__ __forceinline__ void epi(const float acc[8][4], const float* bias,
                                    uint32_t zh[16], uint32_t zl[16], int lane)
{
    int c2 = (lane & 3) * 2;
#pragma unroll
    for (int nt2 = 0; nt2 < 8; nt2++) {
        float2 b = *(const float2*)(bias + nt2 * 8 + c2);
        float t0 = my_tanh(acc[nt2][0] + b.x);
        float t1 = my_tanh(acc[nt2][1] + b.y);
        float t2 = my_tanh(acc[nt2][2] + b.x);
        float t3 = my_tanh(acc[nt2][3] + b.y);
        split2(t0, t1, zh[2 * nt2 + 0], zl[2 * nt2 + 0]);
        split2(t2, t3, zh[2 * nt2 + 1], zl[2 * nt2 + 1]);
    }
}

// ---------------------------------------------------------------------------
__global__ void zero_kernel(void) {
    int i = blockIdx.x * blockDim.x + threadIdx.x;
    if (i < NS * 64) { g_sum_u[i] = 0.0f; g_sum_x[i] = 0.0f; }
    if (i < NS) g_deg[i] = 0.0f;
}

// ---------------------------------------------------------------------------
// s2s: 77->64->64->64. A stride 44 words (88 bf16), W1 stride 44, kchunks=5.
#define S_W1H 0
#define S_W1L 11264
#define S_W2H 22528
#define S_W2L 31744
#define S_W3H 40960
#define S_W3L 50176
#define S_AH  59392
#define S_AL  70656
#define S_B1  81920
#define S_B2  82176
#define S_B3  82432
#define S_DST 82688
#define S2S_SMEM 82944

__global__ void __launch_bounds__(128, 2) s2s_kernel(
    const float* __restrict__ pos_state, const float* __restrict__ xin,
    const float* __restrict__ hbuf,
    const int* __restrict__ esrc, const int* __restrict__ edst,
    const float* __restrict__ edis,
    const float* __restrict__ W1, const float* __restrict__ B1,
    const float* __restrict__ W2, const float* __restrict__ B2,
    const float* __restrict__ W3, const float* __restrict__ B3)
{
    extern __shared__ char sm[];
    uint32_t* W1h = (uint32_t*)(sm + S_W1H);
    uint32_t* W1l = (uint32_t*)(sm + S_W1L);
    uint32_t* W2h = (uint32_t*)(sm + S_W2H);
    uint32_t* W2l = (uint32_t*)(sm + S_W2L);
    uint32_t* W3h = (uint32_t*)(sm + S_W3H);
    uint32_t* W3l = (uint32_t*)(sm + S_W3L);
    uint32_t* Ah  = (uint32_t*)(sm + S_AH);
    uint32_t* Al  = (uint32_t*)(sm + S_AL);
    float* b1 = (float*)(sm + S_B1);
    float* b2 = (float*)(sm + S_B2);
    float* b3 = (float*)(sm + S_B3);
    int* sdst = (int*)(sm + S_DST);
    int tid = threadIdx.x;

    stage_W(W1, W1h, W1l, 77, 44, tid, 128);
    stage_W(W2, W2h, W2l, 64, 36, tid, 128);
    stage_W(W3, W3h, W3l, 64, 36, tid, 128);
    if (tid < 64) { b1[tid] = B1[tid]; b2[tid] = B2[tid]; b3[tid] = B3[tid]; }
    __syncthreads();

    int lane = tid & 31, w = tid >> 5;
    int rowbase = w * 16;
    int g = lane >> 2, c2 = (lane & 3) * 2;
    const int NT = (ES + 63) / 64;

    for (int t = blockIdx.x; t < NT; t += gridDim.x) {
        __syncthreads();
        if (tid < 64) {
            int e = t * 64 + tid;
            bool act = e < ES;
            int ec = act ? e : 0;
            int s = esrc[ec], d = edst[ec];
            uint32_t* rh = Ah + tid * 44;
            uint32_t* rl = Al + tid * 44;
            float2 ps = *(const float2*)(pos_state + 2 * (size_t)s);
            float2 pd = *(const float2*)(pos_state + 2 * (size_t)d);
            float dis = edis[ec];
            const float4* x4 = (const float4*)(xin + 8 * (size_t)s);
            float4 xa = x4[0], xb = x4[1];
            uint32_t hi, lo;
            split2(ps.x, ps.y, hi, lo); rh[0] = hi; rl[0] = lo;
            split2(pd.x, pd.y, hi, lo); rh[1] = hi; rl[1] = lo;
            split2(dis, xa.x, hi, lo);  rh[2] = hi; rl[2] = lo;
            split2(xa.y, xa.z, hi, lo); rh[3] = hi; rl[3] = lo;
            split2(xa.w, xb.x, hi, lo); rh[4] = hi; rl[4] = lo;
            split2(xb.y, xb.z, hi, lo); rh[5] = hi; rl[5] = lo;
            float carry = xb.w;
            const float4* h4 = (const float4*)(hbuf + 64 * (size_t)s);
#pragma unroll 4
            for (int i = 0; i < 16; i++) {
                float4 v = h4[i];
                split2(carry, v.x, hi, lo); rh[6 + 2 * i] = hi; rl[6 + 2 * i] = lo;
                split2(v.y, v.z, hi, lo);   rh[7 + 2 * i] = hi; rl[7 + 2 * i] = lo;
                carry = v.w;
            }
            split2(carry, 0.0f, hi, lo); rh[38] = hi; rl[38] = lo;
            rh[39] = 0; rl[39] = 0;
            sdst[tid] = act ? d : -1;
            if (act) atomicAdd(g_deg + d, 1.0f);
        }
        __syncthreads();

        float acc[8][4];
        uint32_t zh[16], zl[16];
        layer_smem(acc, Ah, Al, 44, rowbase, W1h, W1l, 44, 5, lane);
        epi(acc, b1, zh, zl, lane);
        layer_regs(acc, zh, zl, W2h, W2l, lane);
        epi(acc, b2, zh, zl, lane);
        layer_regs(acc, zh, zl, W3h, W3l, lane);

        int d0 = sdst[rowbase + g], d1 = sdst[rowbase + g + 8];
#pragma unroll
        for (int nt2 = 0; nt2 < 8; nt2++) {
            int col = nt2 * 8 + c2;
            float2 b = *(const float2*)(b3 + col);
            if (d0 >= 0) red2(g_sum_x + (size_t)d0 * 64 + col, acc[nt2][0] + b.x, acc[nt2][1] + b.y);
            if (d1 >= 0) red2(g_sum_x + (size_t)d1 * 64 + col, acc[nt2][2] + b.x, acc[nt2][3] + b.y);
        }
    }
}

// ---------------------------------------------------------------------------
// a2s: 13->64->64->64. A/W1 stride 12 words, kchunks=1.
#define A_W1H 0
#define A_W1L 3072
#define A_W2H 6144
#define A_W2L 15360
#define A_W3H 24576
#define A_W3L 33792
#define A_AH  43008
#define A_AL  46080
#define A_B1  49152
#define A_B2  49408
#define A_B3  49664
#define A_DST 49920
#define A2S_SMEM 50176

__global__ void __launch_bounds__(128, 2) a2s_kernel(
    const float* __restrict__ pos_state, const float* __restrict__ pos_action,
    const float* __restrict__ u,
    const int* __restrict__ esrc, const int* __restrict__ edst,
    const float* __restrict__ edis,
    const float* __restrict__ W1, const float* __restrict__ B1,
    const float* __restrict__ W2, const float* __restrict__ B2,
    const float* __restrict__ W3, const float* __restrict__ B3)
{
    extern __shared__ char sm[];
    uint32_t* W1h = (uint32_t*)(sm + A_W1H);
    uint32_t* W1l = (uint32_t*)(sm + A_W1L);
    uint32_t* W2h = (uint32_t*)(sm + A_W2H);
    uint32_t* W2l = (uint32_t*)(sm + A_W2L);
    uint32_t* W3h = (uint32_t*)(sm + A_W3H);
    uint32_t* W3l = (uint32_t*)(sm + A_W3L);
    uint32_t* Ah  = (uint32_t*)(sm + A_AH);
    uint32_t* Al  = (uint32_t*)(sm + A_AL);
    float* b1 = (float*)(sm + A_B1);
    float* b2 = (float*)(sm + A_B2);
    float* b3 = (float*)(sm + A_B3);
    int* sdst = (int*)(sm + A_DST);
    int tid = threadIdx.x;

    stage_W(W1, W1h, W1l, 13, 12, tid, 128);
    stage_W(W2, W2h, W2l, 64, 36, tid, 128);
    stage_W(W3, W3h, W3l, 64, 36, tid, 128);
    if (tid < 64) { b1[tid] = B1[tid]; b2[tid] = B2[tid]; b3[tid] = B3[tid]; }
    __syncthreads();

    int lane = tid & 31, w = tid >> 5;
    int rowbase = w * 16;
    int g = lane >> 2, c2 = (lane & 3) * 2;
    const int NT = (EA + 63) / 64;

    for (int t = blockIdx.x; t < NT; t += gridDim.x) {
        __syncthreads();
        if (tid < 64) {
            int e = t * 64 + tid;
            bool act = e < EA;
            int ec = act ? e : 0;
            int s = esrc[ec], d = edst[ec];
            uint32_t* rh = Ah + tid * 12;
            uint32_t* rl = Al + tid * 12;
            float2 pa = *(const float2*)(pos_action + 2 * (size_t)s);
            float2 pd = *(const float2*)(pos_state + 2 * (size_t)d);
            float dis = edis[ec];
            const float4* u4 = (const float4*)(u + 8 * (size_t)s);
            float4 ua = u4[0], ub = u4[1];
            uint32_t hi, lo;
            split2(pa.x, pa.y, hi, lo); rh[0] = hi; rl[0] = lo;
            split2(pd.x, pd.y, hi, lo); rh[1] = hi; rl[1] = lo;
            split2(dis, ua.x, hi, lo);  rh[2] = hi; rl[2] = lo;
            split2(ua.y, ua.z, hi, lo); rh[3] = hi; rl[3] = lo;
            split2(ua.w, ub.x, hi, lo); rh[4] = hi; rl[4] = lo;
            split2(ub.y, ub.z, hi, lo); rh[5] = hi; rl[5] = lo;
            split2(ub.w, 0.0f, hi, lo); rh[6] = hi; rl[6] = lo;
            rh[7] = 0; rl[7] = 0;
            sdst[tid] = act ? d : -1;
        }
        __syncthreads();

        float acc[8][4];
        uint32_t zh[16], zl[16];
        layer_smem(acc, Ah, Al, 12, rowbase, W1h, W1l, 12, 1, lane);
        epi(acc, b1, zh, zl, lane);
        layer_regs(acc, zh, zl, W2h, W2l, lane);
        epi(acc, b2, zh, zl, lane);
        layer_regs(acc, zh, zl, W3h, W3l, lane);

        int d0 = sdst[rowbase + g], d1 = sdst[rowbase + g + 8];
#pragma unroll
        for (int nt2 = 0; nt2 < 8; nt2++) {
            int col = nt2 * 8 + c2;
            float2 b = *(const float2*)(b3 + col);
            if (d0 >= 0) red2(g_sum_u + (size_t)d0 * 64 + col, acc[nt2][0] + b.x, acc[nt2][1] + b.y);
            if (d1 >= 0) red2(g_sum_u + (size_t)d1 * 64 + col, acc[nt2][2] + b.x, acc[nt2][3] + b.y);
        }
    }
}

// ---------------------------------------------------------------------------
// upd: 202->64->64->64. A/W1 stride 108 words, kchunks=13.
#define U_W1H 0
#define U_W1L 27648
#define U_W2H 55296
#define U_W2L 64512
#define U_W3H 73728
#define U_W3L 82944
#define U_AH  92160
#define U_AL  119808
#define U_B1  147456
#define U_B2  147712
#define U_B3  147968
#define UPD_SMEM 148224

__global__ void __launch_bounds__(128, 1) upd_kernel(
    const float* __restrict__ pos_state, const float* __restrict__ hbuf,
    const float* __restrict__ xin,
    const float* __restrict__ W1, const float* __restrict__ B1,
    const float* __restrict__ W2, const float* __restrict__ B2,
    const float* __restrict__ W3, const float* __restrict__ B3,
    float* __restrict__ out)
{
    extern __shared__ char sm[];
    uint32_t* W1h = (uint32_t*)(sm + U_W1H);
    uint32_t* W1l = (uint32_t*)(sm + U_W1L);
    uint32_t* W2h = (uint32_t*)(sm + U_W2H);
    uint32_t* W2l = (uint32_t*)(sm + U_W2L);
    uint32_t* W3h = (uint32_t*)(sm + U_W3H);
    uint32_t* W3l = (uint32_t*)(sm + U_W3L);
    uint32_t* Ah  = (uint32_t*)(sm + U_AH);
    uint32_t* Al  = (uint32_t*)(sm + U_AL);
    float* b1 = (float*)(sm + U_B1);
    float* b2 = (float*)(sm + U_B2);
    float* b3 = (float*)(sm + U_B3);
    int tid = threadIdx.x;

    stage_W(W1, W1h, W1l, 202, 108, tid, 128);
    stage_W(W2, W2h, W2l, 64, 36, tid, 128);
    stage_W(W3, W3h, W3l, 64, 36, tid, 128);
    if (tid < 64) { b1[tid] = B1[tid]; b2[tid] = B2[tid]; b3[tid] = B3[tid]; }
    __syncthreads();

    int lane = tid & 31, w = tid >> 5;
    int rowbase = w * 16;
    int g = lane >> 2, c2 = (lane & 3) * 2;
    const int NT = (NS + 63) / 64;

    for (int t = blockIdx.x; t < NT; t += gridDim.x) {
        __syncthreads();
        if (tid < 64) {
            int n = t * 64 + tid;
            int nc = (n < NS) ? n : 0;
            uint32_t* rh = Ah + tid * 108;
            uint32_t* rl = Al + tid * 108;
            float2 ps = *(const float2*)(pos_state + 2 * (size_t)nc);
            const float4* h4  = (const float4*)(hbuf + 64 * (size_t)nc);
            const float4* su4 = (const float4*)(g_sum_u + 64 * (size_t)nc);
            const float4* sx4 = (const float4*)(g_sum_x + 64 * (size_t)nc);
            float inv = rcp_fma(fmaxf(g_deg[nc], 1.0f));
            const float4* x4 = (const float4*)(xin + 8 * (size_t)nc);
            float4 xa = x4[0], xb = x4[1];
            uint32_t hi, lo;
            split2(ps.x, ps.y, hi, lo); rh[0] = hi; rl[0] = lo;
#pragma unroll 4
            for (int i = 0; i < 16; i++) {
                float4 v = h4[i];
                split2(v.x, v.y, hi, lo); rh[1 + 2 * i] = hi; rl[1 + 2 * i] = lo;
                split2(v.z, v.w, hi, lo); rh[2 + 2 * i] = hi; rl[2 + 2 * i] = lo;
            }
#pragma unroll 4
            for (int i = 0; i < 16; i++) {
                float4 v = su4[i];
                split2(v.x, v.y, hi, lo); rh[33 + 2 * i] = hi; rl[33 + 2 * i] = lo;
                split2(v.z, v.w, hi, lo); rh[34 + 2 * i] = hi; rl[34 + 2 * i] = lo;
            }
#pragma unroll 4
            for (int i = 0; i < 16; i++) {
                float4 v = sx4[i];
                split2(v.x * inv, v.y * inv, hi, lo); rh[65 + 2 * i] = hi; rl[65 + 2 * i] = lo;
                split2(v.z * inv, v.w * inv, hi, lo); rh[66 + 2 * i] = hi; rl[66 + 2 * i] = lo;
            }
            split2(xa.x, xa.y, hi, lo); rh[97] = hi;  rl[97] = lo;
            split2(xa.z, xa.w, hi, lo); rh[98] = hi;  rl[98] = lo;
            split2(xb.x, xb.y, hi, lo); rh[99] = hi;  rl[99] = lo;
            split2(xb.z, xb.w, hi, lo); rh[100] = hi; rl[100] = lo;
            rh[101] = 0; rl[101] = 0;
            rh[102] = 0; rl[102] = 0;
            rh[103] = 0; rl[103] = 0;
        }
        __syncthreads();

        float acc[8][4];
        uint32_t zh[16], zl[16];
        layer_smem(acc, Ah, Al, 108, rowbase, W1h, W1l, 108, 13, lane);
        epi(acc, b1, zh, zl, lane);
        layer_regs(acc, zh, zl, W2h, W2l, lane);
        epi(acc, b2, zh, zl, lane);
        layer_regs(acc, zh, zl, W3h, W3l, lane);

        int n0 = t * 64 + rowbase + g;
        int n1 = n0 + 8;
#pragma unroll
        for (int nt2 = 0; nt2 < 8; nt2++) {
            int col = nt2 * 8 + c2;
            float2 b = *(const float2*)(b3 + col);
            if (n0 < NS)
                *(float2*)(out + (size_t)n0 * 64 + col) =
                    make_float2(acc[nt2][0] + b.x, acc[nt2][1] + b.y);
            if (n1 < NS)
                *(float2*)(out + (size_t)n1 * 64 + col) =
                    make_float2(acc[nt2][2] + b.x, acc[nt2][3] + b.y);
        }
    }
}

// ---------------------------------------------------------------------------
extern "C" void kernel_launch(void* const* d_in, const int* in_sizes, int n_in,
                              void* d_out, int out_size) {
    const float* pos_state  = (const float*)d_in[0];
    const float* pos_action = (const float*)d_in[1];
    const float* h          = (const float*)d_in[2];
    const float* x          = (const float*)d_in[3];
    const float* u          = (const float*)d_in[4];
    const int*   a2s_src    = (const int*)d_in[5];
    const int*   a2s_dst    = (const int*)d_in[6];
    const float* a2s_dis    = (const float*)d_in[7];
    const int*   s2s_src    = (const int*)d_in[8];
    const int*   s2s_dst    = (const int*)d_in[9];
    const float* s2s_dis    = (const float*)d_in[10];
    const float* u2h_w1 = (const float*)d_in[11];
    const float* u2h_b1 = (const float*)d_in[12];
    const float* u2h_w2 = (const float*)d_in[13];
    const float* u2h_b2 = (const float*)d_in[14];
    const float* u2h_w3 = (const float*)d_in[15];
    const float* u2h_b3 = (const float*)d_in[16];
    const float* x2h_w1 = (const float*)d_in[17];
    const float* x2h_b1 = (const float*)d_in[18];
    const float* x2h_w2 = (const float*)d_in[19];
    const float* x2h_b2 = (const float*)d_in[20];
    const float* x2h_w3 = (const float*)d_in[21];
    const float* x2h_b3 = (const float*)d_in[22];
    const float* upd_w1 = (const float*)d_in[23];
    const float* upd_b1 = (const float*)d_in[24];
    const float* upd_w2 = (const float*)d_in[25];
    const float* upd_b2 = (const float*)d_in[26];
    const float* upd_w3 = (const float*)d_in[27];
    const float* upd_b3 = (const float*)d_in[28];
    float* out = (float*)d_out;

    cudaFuncSetAttribute(s2s_kernel, cudaFuncAttributeMaxDynamicSharedMemorySize, S2S_SMEM);
    cudaFuncSetAttribute(a2s_kernel, cudaFuncAttributeMaxDynamicSharedMemorySize, A2S_SMEM);
    cudaFuncSetAttribute(upd_kernel, cudaFuncAttributeMaxDynamicSharedMemorySize, UPD_SMEM);

    zero_kernel<<<(NS * 64 + 255) / 256, 256>>>();

    a2s_kernel<<<444, 128, A2S_SMEM>>>(
        pos_state, pos_action, u, a2s_src, a2s_dst, a2s_dis,
        u2h_w1, u2h_b1, u2h_w2, u2h_b2, u2h_w3, u2h_b3);

    s2s_kernel<<<296, 128, S2S_SMEM>>>(
        pos_state, x, h, s2s_src, s2s_dst, s2s_dis,
        x2h_w1, x2h_b1, x2h_w2, x2h_b2, x2h_w3, x2h_b3);

    upd_kernel<<<148, 128, UPD_SMEM>>>(
        pos_state, h, x,
        upd_w1, upd_b1, upd_w2, upd_b2, upd_w3, upd_b3,
        out);
}